// round 1
// baseline (speedup 1.0000x reference)
#include <cuda_runtime.h>
#include <cuda_bf16.h>
#include <math.h>

#define NN 50000
#define NE 600000
#define DD 128
#define NG 64

// ---------------- scratch (device globals; allocation-free) ----------------
__device__ float d_h1lin[(size_t)NN * 512];  // x @ [W1A|W1B|W1C|W1D]
__device__ float d_xcat [(size_t)NN * 512];  // relu(agg1)+b  (concat of 4 convs)
__device__ float d_h2lin[(size_t)NN * 256];  // xcat @ W2
__device__ float d_h2   [(size_t)NN * 256];  // relu(agg2)+b2
__device__ float d_h3lin[(size_t)NN * 128];  // h2 @ W3
__device__ float d_h3   [(size_t)NN * 128];  // agg3 + b3
__device__ float d_disA[NN], d_disB[NN], d_disC[NN], d_disD[NN], d_dis1[NN];
__device__ int   d_cnt[NN];
__device__ int   d_rowptr[NN + 1];
__device__ int   d_wrptr[NN];
__device__ int   d_csr_src[NE];
__device__ int   d_csr_eid[NE];
__device__ int   d_gstart[NG + 1];
__device__ float d_gmat[NG * 256];

// ---------------- setup kernels ----------------
__global__ void k_init() {
    int v = blockIdx.x * blockDim.x + threadIdx.x;
    if (v < NN) {
        d_disA[v] = 1.0f; d_disB[v] = 1.0f; d_disC[v] = 1.0f; d_disD[v] = 1.0f;
        d_dis1[v] = 1.0f;   // self-loop contributes 1 to every degree
        d_cnt[v] = 0;
    }
}

__global__ void k_degree(const int* __restrict__ ei, const float* __restrict__ ea) {
    int e = blockIdx.x * blockDim.x + threadIdx.x;
    if (e >= NE) return;
    int dst = ei[NE + e];
    float4 w = __ldg((const float4*)ea + e);
    atomicAdd(&d_disA[dst], w.x);
    atomicAdd(&d_disB[dst], w.y);
    atomicAdd(&d_disC[dst], w.z);
    atomicAdd(&d_disD[dst], w.w);
    atomicAdd(&d_dis1[dst], 1.0f);
    atomicAdd(&d_cnt[dst], 1);
}

__global__ void k_rsqrt() {
    int v = blockIdx.x * blockDim.x + threadIdx.x;
    if (v < NN) {
        d_disA[v] = rsqrtf(d_disA[v]);
        d_disB[v] = rsqrtf(d_disB[v]);
        d_disC[v] = rsqrtf(d_disC[v]);
        d_disD[v] = rsqrtf(d_disD[v]);
        d_dis1[v] = rsqrtf(d_dis1[v]);
    }
}

// single-block exclusive scan of d_cnt -> d_rowptr / d_wrptr
__global__ void k_scan() {
    __shared__ int wsum[32];
    __shared__ int carry_sh;
    int t = threadIdx.x;
    int lane = t & 31, wid = t >> 5;
    if (t == 0) carry_sh = 0;
    __syncthreads();
    for (int base = 0; base < NN; base += 1024) {
        int idx = base + t;
        int v = (idx < NN) ? d_cnt[idx] : 0;
        int x = v;
        #pragma unroll
        for (int off = 1; off < 32; off <<= 1) {
            int y = __shfl_up_sync(0xffffffffu, x, off);
            if (lane >= off) x += y;
        }
        if (lane == 31) wsum[wid] = x;
        __syncthreads();
        int carry = carry_sh;
        if (wid == 0) {
            int s = wsum[lane];
            #pragma unroll
            for (int off = 1; off < 32; off <<= 1) {
                int y = __shfl_up_sync(0xffffffffu, s, off);
                if (lane >= off) s += y;
            }
            wsum[lane] = s;
        }
        __syncthreads();
        int incl = x + (wid > 0 ? wsum[wid - 1] : 0);
        int excl = incl - v + carry;
        if (idx < NN) { d_rowptr[idx] = excl; d_wrptr[idx] = excl; }
        __syncthreads();
        if (t == 1023) carry_sh = carry + incl;
        __syncthreads();
    }
    if (t == 0) d_rowptr[NN] = carry_sh;
}

__global__ void k_scatter(const int* __restrict__ ei) {
    int e = blockIdx.x * blockDim.x + threadIdx.x;
    if (e >= NE) return;
    int src = ei[e];
    int dst = ei[NE + e];
    int pos = atomicAdd(&d_wrptr[dst], 1);
    d_csr_src[pos] = src;
    d_csr_eid[pos] = e;
}

// ---------------- tiled fp32 GEMM: C[M,N] = A[M,K] @ B[K,N] ----------------
// A stride=K, B stride=N, C stride=ldc (C pointer may carry a column offset)
#define BM 64
#define BN 64
#define BK 16
__global__ __launch_bounds__(256) void sgemm(
    const float* __restrict__ A, const float* __restrict__ B,
    float* __restrict__ C, int M, int N, int K, int ldc)
{
    __shared__ float As[BK][BM];
    __shared__ float Bs[BK][BN];
    int row0 = blockIdx.y * BM, col0 = blockIdx.x * BN;
    int tid = threadIdx.x;
    int tx = tid & 15, ty = tid >> 4;
    float acc[4][4];
    #pragma unroll
    for (int i = 0; i < 4; i++)
        #pragma unroll
        for (int j = 0; j < 4; j++) acc[i][j] = 0.f;

    int ar = tid >> 2;          // 0..63
    int ac = (tid & 3) * 4;     // 0,4,8,12
    int br = tid >> 4;          // 0..15
    int bc = (tid & 15) * 4;    // 0..60

    for (int k0 = 0; k0 < K; k0 += BK) {
        float4 av = make_float4(0.f, 0.f, 0.f, 0.f);
        int grow = row0 + ar;
        if (grow < M) av = *(const float4*)(A + (size_t)grow * K + k0 + ac);
        As[ac + 0][ar] = av.x; As[ac + 1][ar] = av.y;
        As[ac + 2][ar] = av.z; As[ac + 3][ar] = av.w;
        float4 bv = *(const float4*)(B + (size_t)(k0 + br) * N + col0 + bc);
        *(float4*)&Bs[br][bc] = bv;
        __syncthreads();
        #pragma unroll
        for (int kk = 0; kk < BK; kk++) {
            float4 ra = *(const float4*)&As[kk][ty * 4];
            float4 rb = *(const float4*)&Bs[kk][tx * 4];
            acc[0][0] += ra.x * rb.x; acc[0][1] += ra.x * rb.y;
            acc[0][2] += ra.x * rb.z; acc[0][3] += ra.x * rb.w;
            acc[1][0] += ra.y * rb.x; acc[1][1] += ra.y * rb.y;
            acc[1][2] += ra.y * rb.z; acc[1][3] += ra.y * rb.w;
            acc[2][0] += ra.z * rb.x; acc[2][1] += ra.z * rb.y;
            acc[2][2] += ra.z * rb.z; acc[2][3] += ra.z * rb.w;
            acc[3][0] += ra.w * rb.x; acc[3][1] += ra.w * rb.y;
            acc[3][2] += ra.w * rb.z; acc[3][3] += ra.w * rb.w;
        }
        __syncthreads();
    }
    #pragma unroll
    for (int i = 0; i < 4; i++) {
        int r = row0 + ty * 4 + i;
        if (r < M) {
            float4 o = make_float4(acc[i][0], acc[i][1], acc[i][2], acc[i][3]);
            *(float4*)(C + (size_t)r * ldc + col0 + tx * 4) = o;
        }
    }
}

// ---------------- aggregation (gather over CSR, no atomics) ----------------
// conv1: 4 edge-weighted convs fused; input d_h1lin [NN,512], out relu+bias -> d_xcat
__global__ __launch_bounds__(128) void k_agg1(
    const float* __restrict__ ea,
    const float* __restrict__ b1A, const float* __restrict__ b1B,
    const float* __restrict__ b1C, const float* __restrict__ b1D)
{
    int v = blockIdx.x;
    int t = threadIdx.x;
    int beg = d_rowptr[v], end = d_rowptr[v + 1];
    float dAv = d_disA[v], dBv = d_disB[v], dCv = d_disC[v], dDv = d_disD[v];
    float a0 = 0.f, a1 = 0.f, a2 = 0.f, a3 = 0.f;
    for (int p = beg; p < end; ++p) {
        int s = d_csr_src[p];
        int e = d_csr_eid[p];
        float4 w = __ldg((const float4*)ea + e);
        const float* hr = d_h1lin + (size_t)s * 512;
        float nA = d_disA[s] * w.x * dAv;
        float nB = d_disB[s] * w.y * dBv;
        float nC = d_disC[s] * w.z * dCv;
        float nD = d_disD[s] * w.w * dDv;
        a0 += hr[t] * nA;
        a1 += hr[128 + t] * nB;
        a2 += hr[256 + t] * nC;
        a3 += hr[384 + t] * nD;
    }
    const float* hv = d_h1lin + (size_t)v * 512;
    a0 += hv[t] * dAv * dAv;
    a1 += hv[128 + t] * dBv * dBv;
    a2 += hv[256 + t] * dCv * dCv;
    a3 += hv[384 + t] * dDv * dDv;
    float* o = d_xcat + (size_t)v * 512;
    o[t]       = fmaxf(a0 + b1A[t], 0.f);
    o[128 + t] = fmaxf(a1 + b1B[t], 0.f);
    o[256 + t] = fmaxf(a2 + b1C[t], 0.f);
    o[384 + t] = fmaxf(a3 + b1D[t], 0.f);
}

// conv2: unweighted, input d_h2lin [NN,256], out relu+b2 -> d_h2
__global__ __launch_bounds__(128) void k_agg2(const float* __restrict__ b2) {
    int v = blockIdx.x;
    int t = threadIdx.x;
    int beg = d_rowptr[v], end = d_rowptr[v + 1];
    float dv = d_dis1[v];
    float a0 = 0.f, a1 = 0.f;
    for (int p = beg; p < end; ++p) {
        int s = d_csr_src[p];
        float nrm = d_dis1[s] * dv;
        const float* hr = d_h2lin + (size_t)s * 256;
        a0 += hr[t] * nrm;
        a1 += hr[128 + t] * nrm;
    }
    const float* hv = d_h2lin + (size_t)v * 256;
    a0 += hv[t] * dv * dv;
    a1 += hv[128 + t] * dv * dv;
    float* o = d_h2 + (size_t)v * 256;
    o[t]       = fmaxf(a0 + b2[t], 0.f);
    o[128 + t] = fmaxf(a1 + b2[128 + t], 0.f);
}

// conv3: unweighted, input d_h3lin [NN,128], out + b3 (no relu) -> d_h3
__global__ __launch_bounds__(128) void k_agg3(const float* __restrict__ b3) {
    int v = blockIdx.x;
    int t = threadIdx.x;
    int beg = d_rowptr[v], end = d_rowptr[v + 1];
    float dv = d_dis1[v];
    float a0 = 0.f;
    for (int p = beg; p < end; ++p) {
        int s = d_csr_src[p];
        a0 += d_h3lin[(size_t)s * 128 + t] * (d_dis1[s] * dv);
    }
    a0 += d_h3lin[(size_t)v * 128 + t] * dv * dv;
    d_h3[(size_t)v * 128 + t] = a0 + b3[t];
}

// ---------------- pooling + head ----------------
__global__ void k_bounds(const int* __restrict__ batch) {
    int i = blockIdx.x * blockDim.x + threadIdx.x;
    if (i >= NN) return;
    int b = batch[i];
    if (i == 0) {
        for (int g = 0; g <= b; ++g) d_gstart[g] = 0;
    } else {
        int pb = batch[i - 1];
        if (pb != b)
            for (int g = pb + 1; g <= b; ++g) d_gstart[g] = i;
    }
    if (i == NN - 1) {
        for (int g = b + 1; g <= NG; ++g) d_gstart[g] = NN;
    }
}

__global__ __launch_bounds__(128) void k_pool() {
    int g = blockIdx.x;
    int t = threadIdx.x;
    int beg = d_gstart[g], end = d_gstart[g + 1];
    int cnt = end - beg;
    float s = 0.f, m = -INFINITY;
    for (int i = beg; i < end; ++i) {
        float val = d_h3[(size_t)i * 128 + t];
        s += val;
        m = fmaxf(m, val);
    }
    float mean = s / fmaxf((float)cnt, 1.0f);
    if (cnt == 0) m = 0.f;
    d_gmat[g * 256 + t] = mean;
    d_gmat[g * 256 + 128 + t] = m;
}

__global__ void k_mlp(const float* __restrict__ Wm1, const float* __restrict__ bm1,
                      const float* __restrict__ Wm2, const float* __restrict__ bm2,
                      float* __restrict__ out) {
    int g = threadIdx.x;
    if (g >= NG) return;
    const float* gv = d_gmat + g * 256;
    float hid[8];
    #pragma unroll
    for (int j = 0; j < 8; ++j) {
        float s = bm1[j];
        for (int k = 0; k < 256; ++k) s += gv[k] * Wm1[k * 8 + j];
        hid[j] = fmaxf(s, 0.f);
    }
    #pragma unroll
    for (int c = 0; c < 2; ++c) {
        float o = bm2[c];
        #pragma unroll
        for (int j = 0; j < 8; ++j) o += hid[j] * Wm2[j * 2 + c];
        out[g * 2 + c] = o;
    }
}

// ---------------- launch ----------------
extern "C" void kernel_launch(void* const* d_in, const int* in_sizes, int n_in,
                              void* d_out, int out_size) {
    const float* x   = (const float*)d_in[0];
    const int*   ei  = (const int*)d_in[1];
    const float* ea  = (const float*)d_in[2];
    const int*   bat = (const int*)d_in[3];
    const float* W1A = (const float*)d_in[4];  const float* b1A = (const float*)d_in[5];
    const float* W1B = (const float*)d_in[6];  const float* b1B = (const float*)d_in[7];
    const float* W1C = (const float*)d_in[8];  const float* b1C = (const float*)d_in[9];
    const float* W1D = (const float*)d_in[10]; const float* b1D = (const float*)d_in[11];
    const float* W2  = (const float*)d_in[12]; const float* b2  = (const float*)d_in[13];
    const float* W3  = (const float*)d_in[14]; const float* b3  = (const float*)d_in[15];
    const float* Wm1 = (const float*)d_in[16]; const float* bm1 = (const float*)d_in[17];
    const float* Wm2 = (const float*)d_in[18]; const float* bm2 = (const float*)d_in[19];
    float* out = (float*)d_out;

    float *h1lin, *xcat, *h2lin, *h2, *h3lin;
    cudaGetSymbolAddress((void**)&h1lin, d_h1lin);
    cudaGetSymbolAddress((void**)&xcat,  d_xcat);
    cudaGetSymbolAddress((void**)&h2lin, d_h2lin);
    cudaGetSymbolAddress((void**)&h2,    d_h2);
    cudaGetSymbolAddress((void**)&h3lin, d_h3lin);

    const int TB = 256;
    k_init  <<<(NN + TB - 1) / TB, TB>>>();
    k_degree<<<(NE + TB - 1) / TB, TB>>>(ei, ea);
    k_rsqrt <<<(NN + TB - 1) / TB, TB>>>();
    k_scan  <<<1, 1024>>>();
    k_scatter<<<(NE + TB - 1) / TB, TB>>>(ei);

    dim3 gA(128 / BN, (NN + BM - 1) / BM);   // N=128 per conv
    sgemm<<<gA, 256>>>(x, W1A, h1lin + 0,   NN, 128, 128, 512);
    sgemm<<<gA, 256>>>(x, W1B, h1lin + 128, NN, 128, 128, 512);
    sgemm<<<gA, 256>>>(x, W1C, h1lin + 256, NN, 128, 128, 512);
    sgemm<<<gA, 256>>>(x, W1D, h1lin + 384, NN, 128, 128, 512);

    k_agg1<<<NN, 128>>>(ea, b1A, b1B, b1C, b1D);

    dim3 g2(256 / BN, (NN + BM - 1) / BM);
    sgemm<<<g2, 256>>>(xcat, W2, h2lin, NN, 256, 512, 256);
    k_agg2<<<NN, 128>>>(b2);

    dim3 g3(128 / BN, (NN + BM - 1) / BM);
    sgemm<<<g3, 256>>>(h2, W3, h3lin, NN, 128, 256, 128);
    k_agg3<<<NN, 128>>>(b3);

    k_bounds<<<(NN + TB - 1) / TB, TB>>>(bat);
    k_pool<<<NG, 128>>>();
    k_mlp<<<1, NG>>>(Wm1, bm1, Wm2, bm2, out);
}

// round 2
// speedup vs baseline: 1.1236x; 1.1236x over previous
#include <cuda_runtime.h>
#include <cuda_bf16.h>
#include <math.h>

#define NN 50000
#define NE 600000
#define DD 128
#define NG 64

typedef unsigned long long u64;

// ---------------- scratch (device globals; allocation-free) ----------------
__device__ float d_h1lin[(size_t)NN * 512];  // x @ Wcat
__device__ float d_xcat [(size_t)NN * 512];  // relu(agg1)+b
__device__ float d_h2lin[(size_t)NN * 256];
__device__ float d_h2   [(size_t)NN * 256];
__device__ float d_h3lin[(size_t)NN * 128];
__device__ float d_h3   [(size_t)NN * 128];
__device__ float d_Wcat [128 * 512];
__device__ float d_disA[NN], d_disB[NN], d_disC[NN], d_disD[NN], d_dis1[NN];
__device__ int   d_cnt[NN];
__device__ int   d_rowptr[NN + 1];
__device__ int   d_wrptr[NN];
__device__ int   d_csr_src[NE];
__device__ int   d_csr_eid[NE];
__device__ int   d_bsum[256];
__device__ int   d_boff[256];
__device__ int   d_gstart[NG + 1];
__device__ float d_gmat[NG * 256];

// ---------------- f32x2 helpers ----------------
__device__ __forceinline__ u64 pack2(float lo, float hi) {
    u64 r; asm("mov.b64 %0, {%1,%2};" : "=l"(r) : "f"(lo), "f"(hi)); return r;
}
__device__ __forceinline__ void fma2(u64& d, u64 a, u64 b) {
    asm("fma.rn.f32x2 %0, %1, %2, %0;" : "+l"(d) : "l"(a), "l"(b));
}

// ---------------- setup: init degrees + pack Wcat ----------------
__global__ void k_init(const float* __restrict__ WA, const float* __restrict__ WB,
                       const float* __restrict__ WC, const float* __restrict__ WD) {
    int b = blockIdx.x;
    if (b < 196) {
        int v = b * 256 + threadIdx.x;
        if (v < NN) {
            d_disA[v] = 1.0f; d_disB[v] = 1.0f; d_disC[v] = 1.0f; d_disD[v] = 1.0f;
            d_dis1[v] = 1.0f;
            d_cnt[v] = 0;
        }
    } else {
        int i = (b - 196) * 256 + threadIdx.x;   // 0..16383
        int k = i >> 7, c = i & 127;
        d_Wcat[k * 512 +   0 + c] = WA[i];
        d_Wcat[k * 512 + 128 + c] = WB[i];
        d_Wcat[k * 512 + 256 + c] = WC[i];
        d_Wcat[k * 512 + 384 + c] = WD[i];
    }
}

__global__ void k_degree(const int* __restrict__ ei, const float* __restrict__ ea) {
    int e = blockIdx.x * blockDim.x + threadIdx.x;
    if (e >= NE) return;
    int dst = ei[NE + e];
    float4 w = __ldg((const float4*)ea + e);
    atomicAdd(&d_disA[dst], w.x);
    atomicAdd(&d_disB[dst], w.y);
    atomicAdd(&d_disC[dst], w.z);
    atomicAdd(&d_disD[dst], w.w);
    atomicAdd(&d_dis1[dst], 1.0f);
    atomicAdd(&d_cnt[dst], 1);
}

__global__ void k_rsqrt() {
    int v = blockIdx.x * blockDim.x + threadIdx.x;
    if (v < NN) {
        d_disA[v] = rsqrtf(d_disA[v]);
        d_disB[v] = rsqrtf(d_disB[v]);
        d_disC[v] = rsqrtf(d_disC[v]);
        d_disD[v] = rsqrtf(d_disD[v]);
        d_dis1[v] = rsqrtf(d_dis1[v]);
    }
}

// ---------------- 3-phase grid scan of d_cnt -> d_rowptr ----------------
__global__ void k_bsum() {   // 196 blocks x 256
    __shared__ int ws[8];
    int idx = blockIdx.x * 256 + threadIdx.x;
    int v = (idx < NN) ? d_cnt[idx] : 0;
    int lane = threadIdx.x & 31, wid = threadIdx.x >> 5;
    int s = v;
    #pragma unroll
    for (int o = 16; o > 0; o >>= 1) s += __shfl_down_sync(0xffffffffu, s, o);
    if (lane == 0) ws[wid] = s;
    __syncthreads();
    if (wid == 0) {
        int t = (lane < 8) ? ws[lane] : 0;
        #pragma unroll
        for (int o = 4; o > 0; o >>= 1) t += __shfl_down_sync(0xffffffffu, t, o);
        if (lane == 0) d_bsum[blockIdx.x] = t;
    }
}

__global__ void k_bscan() {  // 1 block x 256: exclusive scan of 196 sums
    __shared__ int ws[8];
    int t = threadIdx.x;
    int lane = t & 31, wid = t >> 5;
    int v = (t < 196) ? d_bsum[t] : 0;
    int x = v;
    #pragma unroll
    for (int o = 1; o < 32; o <<= 1) {
        int y = __shfl_up_sync(0xffffffffu, x, o);
        if (lane >= o) x += y;
    }
    if (lane == 31) ws[wid] = x;
    __syncthreads();
    if (wid == 0 && lane < 8) {
        int s = ws[lane];
        #pragma unroll
        for (int o = 1; o < 8; o <<= 1) {
            int y = __shfl_up_sync(0xffu, s, o);
            if (lane >= o) s += y;
        }
        ws[lane] = s;
    }
    __syncthreads();
    int excl = x - v + (wid > 0 ? ws[wid - 1] : 0);
    if (t < 196) d_boff[t] = excl;
    if (t == 0) d_rowptr[NN] = NE;
}

__global__ void k_scan3() {  // 196 blocks x 256: per-block scan + offset
    __shared__ int ws[8];
    int idx = blockIdx.x * 256 + threadIdx.x;
    int t = threadIdx.x;
    int lane = t & 31, wid = t >> 5;
    int v = (idx < NN) ? d_cnt[idx] : 0;
    int x = v;
    #pragma unroll
    for (int o = 1; o < 32; o <<= 1) {
        int y = __shfl_up_sync(0xffffffffu, x, o);
        if (lane >= o) x += y;
    }
    if (lane == 31) ws[wid] = x;
    __syncthreads();
    if (wid == 0 && lane < 8) {
        int s = ws[lane];
        #pragma unroll
        for (int o = 1; o < 8; o <<= 1) {
            int y = __shfl_up_sync(0xffu, s, o);
            if (lane >= o) s += y;
        }
        ws[lane] = s;
    }
    __syncthreads();
    int excl = x - v + (wid > 0 ? ws[wid - 1] : 0) + d_boff[blockIdx.x];
    if (idx < NN) { d_rowptr[idx] = excl; d_wrptr[idx] = excl; }
}

__global__ void k_scatter(const int* __restrict__ ei) {
    int e = blockIdx.x * blockDim.x + threadIdx.x;
    if (e >= NE) return;
    int src = ei[e];
    int dst = ei[NE + e];
    int pos = atomicAdd(&d_wrptr[dst], 1);
    d_csr_src[pos] = src;
    d_csr_eid[pos] = e;
}

// -------- fp32 GEMM via fma.rn.f32x2: C[M,N] = A[M,K] @ B[K,N] --------
// 128x128 tile, BK=16, 256 threads, 8x8 microtile, double-buffered smem.
#define GBM 128
#define GBN 128
#define GBK 16
__global__ __launch_bounds__(256, 2) void sgemm2(
    const float* __restrict__ A, const float* __restrict__ B,
    float* __restrict__ C, int M, int N, int K, int ldc)
{
    __shared__ float As[2][GBK][132];
    __shared__ float Bs[2][GBK][128];
    int row0 = blockIdx.y * GBM, col0 = blockIdx.x * GBN;
    int tid = threadIdx.x;
    int tx = tid & 15, ty = tid >> 4;

    int a_r = tid >> 2;             // 0..63  -> rows a_r, a_r+64
    int a_c = (tid & 3) << 2;       // 0,4,8,12
    int b_r = tid >> 5;             // 0..7   -> rows b_r, b_r+8
    int b_c = (tid & 31) << 2;      // 0..124

    u64 acc[8][4];
    #pragma unroll
    for (int i = 0; i < 8; i++)
        #pragma unroll
        for (int j = 0; j < 4; j++) acc[i][j] = 0ull;

    float4 aR0, aR1, bR0, bR1;
    // initial tile load (k0 = 0)
    {
        int r0 = row0 + a_r, r1 = row0 + a_r + 64;
        aR0 = (r0 < M) ? *(const float4*)(A + (size_t)r0 * K + a_c) : make_float4(0,0,0,0);
        aR1 = (r1 < M) ? *(const float4*)(A + (size_t)r1 * K + a_c) : make_float4(0,0,0,0);
        bR0 = *(const float4*)(B + (size_t)b_r * N + col0 + b_c);
        bR1 = *(const float4*)(B + (size_t)(b_r + 8) * N + col0 + b_c);
    }
    // store buffer 0
    As[0][a_c + 0][a_r] = aR0.x; As[0][a_c + 1][a_r] = aR0.y;
    As[0][a_c + 2][a_r] = aR0.z; As[0][a_c + 3][a_r] = aR0.w;
    As[0][a_c + 0][a_r + 64] = aR1.x; As[0][a_c + 1][a_r + 64] = aR1.y;
    As[0][a_c + 2][a_r + 64] = aR1.z; As[0][a_c + 3][a_r + 64] = aR1.w;
    *(float4*)&Bs[0][b_r][b_c] = bR0;
    *(float4*)&Bs[0][b_r + 8][b_c] = bR1;
    __syncthreads();

    int nk = K / GBK;
    for (int kt = 0; kt < nk; ++kt) {
        int buf = kt & 1;
        if (kt + 1 < nk) {
            int k0 = (kt + 1) * GBK;
            int r0 = row0 + a_r, r1 = row0 + a_r + 64;
            aR0 = (r0 < M) ? *(const float4*)(A + (size_t)r0 * K + k0 + a_c) : make_float4(0,0,0,0);
            aR1 = (r1 < M) ? *(const float4*)(A + (size_t)r1 * K + k0 + a_c) : make_float4(0,0,0,0);
            bR0 = *(const float4*)(B + (size_t)(k0 + b_r) * N + col0 + b_c);
            bR1 = *(const float4*)(B + (size_t)(k0 + b_r + 8) * N + col0 + b_c);
        }
        #pragma unroll
        for (int kk = 0; kk < GBK; kk++) {
            float4 a03 = *(const float4*)&As[buf][kk][ty * 8];
            float4 a47 = *(const float4*)&As[buf][kk][ty * 8 + 4];
            ulonglong2 bA = *(const ulonglong2*)&Bs[buf][kk][tx * 8];
            ulonglong2 bB = *(const ulonglong2*)&Bs[buf][kk][tx * 8 + 4];
            float av[8] = {a03.x, a03.y, a03.z, a03.w, a47.x, a47.y, a47.z, a47.w};
            #pragma unroll
            for (int i = 0; i < 8; i++) {
                u64 ai = pack2(av[i], av[i]);
                fma2(acc[i][0], ai, bA.x);
                fma2(acc[i][1], ai, bA.y);
                fma2(acc[i][2], ai, bB.x);
                fma2(acc[i][3], ai, bB.y);
            }
        }
        if (kt + 1 < nk) {
            int nb = buf ^ 1;
            As[nb][a_c + 0][a_r] = aR0.x; As[nb][a_c + 1][a_r] = aR0.y;
            As[nb][a_c + 2][a_r] = aR0.z; As[nb][a_c + 3][a_r] = aR0.w;
            As[nb][a_c + 0][a_r + 64] = aR1.x; As[nb][a_c + 1][a_r + 64] = aR1.y;
            As[nb][a_c + 2][a_r + 64] = aR1.z; As[nb][a_c + 3][a_r + 64] = aR1.w;
            *(float4*)&Bs[nb][b_r][b_c] = bR0;
            *(float4*)&Bs[nb][b_r + 8][b_c] = bR1;
            __syncthreads();
        }
    }

    #pragma unroll
    for (int i = 0; i < 8; i++) {
        int r = row0 + ty * 8 + i;
        if (r < M) {
            ulonglong2 s0, s1;
            s0.x = acc[i][0]; s0.y = acc[i][1];
            s1.x = acc[i][2]; s1.y = acc[i][3];
            *(ulonglong2*)(C + (size_t)r * ldc + col0 + tx * 8) = s0;
            *(ulonglong2*)(C + (size_t)r * ldc + col0 + tx * 8 + 4) = s1;
        }
    }
}

// ---------------- aggregation (gather over CSR, no atomics) ----------------
__global__ __launch_bounds__(128) void k_agg1(
    const float* __restrict__ ea,
    const float* __restrict__ b1A, const float* __restrict__ b1B,
    const float* __restrict__ b1C, const float* __restrict__ b1D)
{
    int v = blockIdx.x;
    int t = threadIdx.x;
    int beg = d_rowptr[v], end = d_rowptr[v + 1];
    float dAv = d_disA[v], dBv = d_disB[v], dCv = d_disC[v], dDv = d_disD[v];
    float a0 = 0.f, a1 = 0.f, a2 = 0.f, a3 = 0.f;
    for (int p = beg; p < end; ++p) {
        int s = d_csr_src[p];
        int e = d_csr_eid[p];
        float4 w = __ldg((const float4*)ea + e);
        const float* hr = d_h1lin + (size_t)s * 512;
        float nA = d_disA[s] * w.x * dAv;
        float nB = d_disB[s] * w.y * dBv;
        float nC = d_disC[s] * w.z * dCv;
        float nD = d_disD[s] * w.w * dDv;
        a0 += hr[t] * nA;
        a1 += hr[128 + t] * nB;
        a2 += hr[256 + t] * nC;
        a3 += hr[384 + t] * nD;
    }
    const float* hv = d_h1lin + (size_t)v * 512;
    a0 += hv[t] * dAv * dAv;
    a1 += hv[128 + t] * dBv * dBv;
    a2 += hv[256 + t] * dCv * dCv;
    a3 += hv[384 + t] * dDv * dDv;
    float* o = d_xcat + (size_t)v * 512;
    o[t]       = fmaxf(a0 + b1A[t], 0.f);
    o[128 + t] = fmaxf(a1 + b1B[t], 0.f);
    o[256 + t] = fmaxf(a2 + b1C[t], 0.f);
    o[384 + t] = fmaxf(a3 + b1D[t], 0.f);
}

__global__ __launch_bounds__(128) void k_agg2(const float* __restrict__ b2) {
    int v = blockIdx.x;
    int t = threadIdx.x;
    int beg = d_rowptr[v], end = d_rowptr[v + 1];
    float dv = d_dis1[v];
    float a0 = 0.f, a1 = 0.f;
    for (int p = beg; p < end; ++p) {
        int s = d_csr_src[p];
        float nrm = d_dis1[s] * dv;
        const float* hr = d_h2lin + (size_t)s * 256;
        a0 += hr[t] * nrm;
        a1 += hr[128 + t] * nrm;
    }
    const float* hv = d_h2lin + (size_t)v * 256;
    a0 += hv[t] * dv * dv;
    a1 += hv[128 + t] * dv * dv;
    float* o = d_h2 + (size_t)v * 256;
    o[t]       = fmaxf(a0 + b2[t], 0.f);
    o[128 + t] = fmaxf(a1 + b2[128 + t], 0.f);
}

__global__ __launch_bounds__(128) void k_agg3(const float* __restrict__ b3) {
    int v = blockIdx.x;
    int t = threadIdx.x;
    int beg = d_rowptr[v], end = d_rowptr[v + 1];
    float dv = d_dis1[v];
    float a0 = 0.f;
    for (int p = beg; p < end; ++p) {
        int s = d_csr_src[p];
        a0 += d_h3lin[(size_t)s * 128 + t] * (d_dis1[s] * dv);
    }
    a0 += d_h3lin[(size_t)v * 128 + t] * dv * dv;
    d_h3[(size_t)v * 128 + t] = a0 + b3[t];
}

// ---------------- pooling + head ----------------
__global__ void k_bounds(const int* __restrict__ batch) {
    int i = blockIdx.x * blockDim.x + threadIdx.x;
    if (i >= NN) return;
    int b = batch[i];
    if (i == 0) {
        for (int g = 0; g <= b; ++g) d_gstart[g] = 0;
    } else {
        int pb = batch[i - 1];
        if (pb != b)
            for (int g = pb + 1; g <= b; ++g) d_gstart[g] = i;
    }
    if (i == NN - 1) {
        for (int g = b + 1; g <= NG; ++g) d_gstart[g] = NN;
    }
}

__global__ __launch_bounds__(128) void k_pool() {
    int g = blockIdx.x;
    int t = threadIdx.x;
    int beg = d_gstart[g], end = d_gstart[g + 1];
    int cnt = end - beg;
    float s = 0.f, m = -INFINITY;
    for (int i = beg; i < end; ++i) {
        float val = d_h3[(size_t)i * 128 + t];
        s += val;
        m = fmaxf(m, val);
    }
    float mean = s / fmaxf((float)cnt, 1.0f);
    if (cnt == 0) m = 0.f;
    d_gmat[g * 256 + t] = mean;
    d_gmat[g * 256 + 128 + t] = m;
}

__global__ void k_mlp(const float* __restrict__ Wm1, const float* __restrict__ bm1,
                      const float* __restrict__ Wm2, const float* __restrict__ bm2,
                      float* __restrict__ out) {
    int g = threadIdx.x;
    if (g >= NG) return;
    const float* gv = d_gmat + g * 256;
    float hid[8];
    #pragma unroll
    for (int j = 0; j < 8; ++j) {
        float s = bm1[j];
        for (int k = 0; k < 256; ++k) s += gv[k] * Wm1[k * 8 + j];
        hid[j] = fmaxf(s, 0.f);
    }
    #pragma unroll
    for (int c = 0; c < 2; ++c) {
        float o = bm2[c];
        #pragma unroll
        for (int j = 0; j < 8; ++j) o += hid[j] * Wm2[j * 2 + c];
        out[g * 2 + c] = o;
    }
}

// ---------------- launch ----------------
extern "C" void kernel_launch(void* const* d_in, const int* in_sizes, int n_in,
                              void* d_out, int out_size) {
    const float* x   = (const float*)d_in[0];
    const int*   ei  = (const int*)d_in[1];
    const float* ea  = (const float*)d_in[2];
    const int*   bat = (const int*)d_in[3];
    const float* W1A = (const float*)d_in[4];  const float* b1A = (const float*)d_in[5];
    const float* W1B = (const float*)d_in[6];  const float* b1B = (const float*)d_in[7];
    const float* W1C = (const float*)d_in[8];  const float* b1C = (const float*)d_in[9];
    const float* W1D = (const float*)d_in[10]; const float* b1D = (const float*)d_in[11];
    const float* W2  = (const float*)d_in[12]; const float* b2  = (const float*)d_in[13];
    const float* W3  = (const float*)d_in[14]; const float* b3  = (const float*)d_in[15];
    const float* Wm1 = (const float*)d_in[16]; const float* bm1 = (const float*)d_in[17];
    const float* Wm2 = (const float*)d_in[18]; const float* bm2 = (const float*)d_in[19];
    float* out = (float*)d_out;

    float *h1lin, *xcat, *h2lin, *h2, *h3lin, *Wcat;
    cudaGetSymbolAddress((void**)&h1lin, d_h1lin);
    cudaGetSymbolAddress((void**)&xcat,  d_xcat);
    cudaGetSymbolAddress((void**)&h2lin, d_h2lin);
    cudaGetSymbolAddress((void**)&h2,    d_h2);
    cudaGetSymbolAddress((void**)&h3lin, d_h3lin);
    cudaGetSymbolAddress((void**)&Wcat,  d_Wcat);

    const int TB = 256;
    k_init  <<<196 + 64, 256>>>(W1A, W1B, W1C, W1D);               // launch 1
    k_degree<<<(NE + TB - 1) / TB, TB>>>(ei, ea);                  // launch 2
    k_rsqrt <<<(NN + TB - 1) / TB, TB>>>();                        // launch 3

    // launch 4 — the big fused GEMM (profiled slot)
    sgemm2<<<dim3(512 / GBN, (NN + GBM - 1) / GBM), 256>>>(x, Wcat, h1lin, NN, 512, 128, 512);

    k_bsum  <<<196, 256>>>();
    k_bscan <<<1, 256>>>();
    k_scan3 <<<196, 256>>>();
    k_scatter<<<(NE + TB - 1) / TB, TB>>>(ei);

    k_agg1<<<NN, 128>>>(ea, b1A, b1B, b1C, b1D);

    sgemm2<<<dim3(256 / GBN, (NN + GBM - 1) / GBM), 256>>>(xcat, W2, h2lin, NN, 256, 512, 256);
    k_agg2<<<NN, 128>>>(b2);

    sgemm2<<<dim3(128 / GBN, (NN + GBM - 1) / GBM), 256>>>(h2, W3, h3lin, NN, 128, 256, 128);
    k_agg3<<<NN, 128>>>(b3);

    k_bounds<<<(NN + TB - 1) / TB, TB>>>(bat);
    k_pool<<<NG, 128>>>();
    k_mlp<<<1, NG>>>(Wm1, bm1, Wm2, bm2, out);
}

// round 4
// speedup vs baseline: 1.6245x; 1.4458x over previous
#include <cuda_runtime.h>
#include <cuda_bf16.h>
#include <math.h>
#include <cstdint>

#define NN 50000
#define NE 600000
#define NG 64

typedef unsigned long long u64;
typedef unsigned int u32;

// ---------------- scratch (device globals; allocation-free) ----------------
__device__ float d_h1lin[(size_t)NN * 512];
__device__ float d_xcat [(size_t)NN * 512];
__device__ float d_h2lin[(size_t)NN * 256];
__device__ float d_h2   [(size_t)NN * 256];
__device__ float d_h3lin[(size_t)NN * 128];
__device__ float d_h3   [(size_t)NN * 128];
__device__ unsigned short d_wc_hi[512 * 128], d_wc_lo[512 * 128];   // Bt[N=512,K=128]
__device__ unsigned short d_w2_hi[256 * 512], d_w2_lo[256 * 512];   // Bt[N=256,K=512]
__device__ unsigned short d_w3_hi[128 * 256], d_w3_lo[128 * 256];   // Bt[N=128,K=256]
__device__ float d_dis4[4 * NN];      // seg-major: d_dis4[seg*NN + v]
__device__ float d_dis1[NN];
__device__ int   d_cnt[NN];
__device__ int   d_rowptr[NN + 1];
__device__ int   d_wrptr[NN];
__device__ int   d_csr_src[NE];
__device__ int   d_csr_eid[NE];
__device__ int   d_bsum[256];
__device__ int   d_boff[256];
__device__ int   d_gstart[NG + 1];
__device__ float d_gmat[NG * 256];

#define CVT_BF16X2(res, a, b) asm("cvt.rn.bf16x2.f32 %0, %1, %2;" : "=r"(res) : "f"(b), "f"(a))

// fp32 -> (hi bf16 trunc, lo bf16 rn) split
__device__ __forceinline__ void splitf(float a, unsigned short& h, unsigned short& l) {
    u32 u = __float_as_uint(a);
    h = (unsigned short)(u >> 16);
    float lf = a - __uint_as_float(u & 0xffff0000u);
    __nv_bfloat16 lb = __float2bfloat16(lf);
    l = *reinterpret_cast<unsigned short*>(&lb);
}

__device__ __forceinline__ void mma_bf16(float* d, const u32* a, const u32* b) {
    asm volatile(
        "mma.sync.aligned.m16n8k16.row.col.f32.bf16.bf16.f32 "
        "{%0,%1,%2,%3}, {%4,%5,%6,%7}, {%8,%9}, {%0,%1,%2,%3};"
        : "+f"(d[0]), "+f"(d[1]), "+f"(d[2]), "+f"(d[3])
        : "r"(a[0]), "r"(a[1]), "r"(a[2]), "r"(a[3]), "r"(b[0]), "r"(b[1]));
}

// ---------------- setup: init degrees + weight transpose/split ----------------
__global__ void k_init(const float* __restrict__ WA, const float* __restrict__ WB,
                       const float* __restrict__ WC, const float* __restrict__ WD,
                       const float* __restrict__ W2, const float* __restrict__ W3) {
    int b = blockIdx.x;
    if (b < 196) {
        int v = b * 256 + threadIdx.x;
        if (v < NN) {
            d_dis4[v] = 1.0f; d_dis4[NN + v] = 1.0f;
            d_dis4[2 * NN + v] = 1.0f; d_dis4[3 * NN + v] = 1.0f;
            d_dis1[v] = 1.0f;
            d_cnt[v] = 0;
        }
        return;
    }
    int i = (b - 196) * 256 + threadIdx.x;   // 0 .. 229375
    float v; unsigned short h, l;
    if (i < 65536) {                 // Wcat_t [512,128]: n = conv*128+c
        int n = i >> 7, kk = i & 127;
        int conv = n >> 7, c = n & 127;
        const float* W = (conv == 0) ? WA : (conv == 1) ? WB : (conv == 2) ? WC : WD;
        v = W[kk * 128 + c];
        splitf(v, h, l);
        d_wc_hi[i] = h; d_wc_lo[i] = l;
    } else if (i < 65536 + 131072) { // W2t [256,512]
        int j = i - 65536;
        int n = j >> 9, kk = j & 511;
        v = W2[kk * 256 + n];
        splitf(v, h, l);
        d_w2_hi[j] = h; d_w2_lo[j] = l;
    } else {                          // W3t [128,256]
        int j = i - 196608;
        int n = j >> 8, kk = j & 255;
        v = W3[kk * 128 + n];
        splitf(v, h, l);
        d_w3_hi[j] = h; d_w3_lo[j] = l;
    }
}

__global__ void k_degree(const int* __restrict__ ei, const float* __restrict__ ea) {
    int e = blockIdx.x * blockDim.x + threadIdx.x;
    if (e >= NE) return;
    int dst = ei[NE + e];
    float4 w = __ldg((const float4*)ea + e);
    atomicAdd(&d_dis4[dst], w.x);
    atomicAdd(&d_dis4[NN + dst], w.y);
    atomicAdd(&d_dis4[2 * NN + dst], w.z);
    atomicAdd(&d_dis4[3 * NN + dst], w.w);
    atomicAdd(&d_dis1[dst], 1.0f);
    atomicAdd(&d_cnt[dst], 1);
}

__global__ void k_rsqrt() {
    int v = blockIdx.x * blockDim.x + threadIdx.x;
    if (v < 4 * NN) d_dis4[v] = rsqrtf(d_dis4[v]);
    else if (v < 5 * NN) d_dis1[v - 4 * NN] = rsqrtf(d_dis1[v - 4 * NN]);
}

// ---------------- 3-phase grid scan of d_cnt -> d_rowptr ----------------
__global__ void k_bsum() {
    __shared__ int ws[8];
    int idx = blockIdx.x * 256 + threadIdx.x;
    int v = (idx < NN) ? d_cnt[idx] : 0;
    int lane = threadIdx.x & 31, wid = threadIdx.x >> 5;
    int s = v;
    #pragma unroll
    for (int o = 16; o > 0; o >>= 1) s += __shfl_down_sync(0xffffffffu, s, o);
    if (lane == 0) ws[wid] = s;
    __syncthreads();
    if (wid == 0) {
        int t = (lane < 8) ? ws[lane] : 0;
        #pragma unroll
        for (int o = 4; o > 0; o >>= 1) t += __shfl_down_sync(0xffffffffu, t, o);
        if (lane == 0) d_bsum[blockIdx.x] = t;
    }
}

__global__ void k_bscan() {
    __shared__ int ws[8];
    int t = threadIdx.x;
    int lane = t & 31, wid = t >> 5;
    int v = (t < 196) ? d_bsum[t] : 0;
    int x = v;
    #pragma unroll
    for (int o = 1; o < 32; o <<= 1) {
        int y = __shfl_up_sync(0xffffffffu, x, o);
        if (lane >= o) x += y;
    }
    if (lane == 31) ws[wid] = x;
    __syncthreads();
    if (wid == 0 && lane < 8) {
        int s = ws[lane];
        #pragma unroll
        for (int o = 1; o < 8; o <<= 1) {
            int y = __shfl_up_sync(0xffu, s, o);
            if (lane >= o) s += y;
        }
        ws[lane] = s;
    }
    __syncthreads();
    int excl = x - v + (wid > 0 ? ws[wid - 1] : 0);
    if (t < 196) d_boff[t] = excl;
    if (t == 0) d_rowptr[NN] = NE;
}

__global__ void k_scan3() {
    __shared__ int ws[8];
    int idx = blockIdx.x * 256 + threadIdx.x;
    int t = threadIdx.x;
    int lane = t & 31, wid = t >> 5;
    int v = (idx < NN) ? d_cnt[idx] : 0;
    int x = v;
    #pragma unroll
    for (int o = 1; o < 32; o <<= 1) {
        int y = __shfl_up_sync(0xffffffffu, x, o);
        if (lane >= o) x += y;
    }
    if (lane == 31) ws[wid] = x;
    __syncthreads();
    if (wid == 0 && lane < 8) {
        int s = ws[lane];
        #pragma unroll
        for (int o = 1; o < 8; o <<= 1) {
            int y = __shfl_up_sync(0xffu, s, o);
            if (lane >= o) s += y;
        }
        ws[lane] = s;
    }
    __syncthreads();
    int excl = x - v + (wid > 0 ? ws[wid - 1] : 0) + d_boff[blockIdx.x];
    if (idx < NN) { d_rowptr[idx] = excl; d_wrptr[idx] = excl; }
}

__global__ void k_scatter(const int* __restrict__ ei) {
    int e = blockIdx.x * blockDim.x + threadIdx.x;
    if (e >= NE) return;
    int src = ei[e];
    int dst = ei[NE + e];
    int pos = atomicAdd(&d_wrptr[dst], 1);
    d_csr_src[pos] = src;
    d_csr_eid[pos] = e;
}

// ============ mma.sync split-bf16 GEMM: C[M,:] tile = A[M,K] @ Bt[N,K]^T ============
// 128x128 block tile, BK=32, 256 threads = 8 warps (2x4), warp tile 64x32.
#define KT 32
#define ASTR 40   // smem row stride in bf16 elems (conflict-free frag loads)

__global__ __launch_bounds__(256, 1) void mma_gemm(
    const float* __restrict__ A, const unsigned short* __restrict__ Bhi,
    const unsigned short* __restrict__ Blo, float* __restrict__ C,
    int M, int K, int ldc)
{
    __shared__ unsigned short sAh[128 * ASTR], sAl[128 * ASTR];
    __shared__ unsigned short sBh[128 * ASTR], sBl[128 * ASTR];
    int tid = threadIdx.x;
    int wid = tid >> 5, lane = tid & 31;
    int g = lane >> 2, tg = lane & 3;
    int wm = wid >> 2, wn = wid & 3;
    int row0 = blockIdx.y * 128, col0 = blockIdx.x * 128;

    float c[4][4][4];
    #pragma unroll
    for (int mi = 0; mi < 4; mi++)
        #pragma unroll
        for (int ni = 0; ni < 4; ni++)
            #pragma unroll
            for (int q = 0; q < 4; q++) c[mi][ni][q] = 0.f;

    for (int kc = 0; kc < K; kc += KT) {
        // ---- A fill: 128x32 fp32 -> hi/lo bf16 ----
        #pragma unroll
        for (int i = 0; i < 4; i++) {
            int cdx = tid + i * 256;           // 0..1023
            int row = cdx >> 3, kf = cdx & 7;
            int gr = row0 + row;
            float4 f = (gr < M) ? *(const float4*)(A + (size_t)gr * K + kc + kf * 4)
                                : make_float4(0.f, 0.f, 0.f, 0.f);
            u32 u0 = __float_as_uint(f.x), u1 = __float_as_uint(f.y);
            u32 u2 = __float_as_uint(f.z), u3 = __float_as_uint(f.w);
            u32 hi01 = (u0 >> 16) | (u1 & 0xffff0000u);
            u32 hi23 = (u2 >> 16) | (u3 & 0xffff0000u);
            float l0 = f.x - __uint_as_float(u0 & 0xffff0000u);
            float l1 = f.y - __uint_as_float(u1 & 0xffff0000u);
            float l2 = f.z - __uint_as_float(u2 & 0xffff0000u);
            float l3 = f.w - __uint_as_float(u3 & 0xffff0000u);
            u32 lo01, lo23;
            CVT_BF16X2(lo01, l0, l1);
            CVT_BF16X2(lo23, l2, l3);
            int off = row * ASTR + kf * 4;
            *(uint2*)&sAh[off] = make_uint2(hi01, hi23);
            *(uint2*)&sAl[off] = make_uint2(lo01, lo23);
        }
        // ---- B fill: 128x32 pre-split bf16 ----
        #pragma unroll
        for (int i = 0; i < 2; i++) {
            int cdx = tid + i * 256;           // 0..511
            int row = cdx >> 2, k8 = cdx & 3;
            size_t gi = (size_t)(col0 + row) * K + kc + k8 * 8;
            uint4 vh = *(const uint4*)(Bhi + gi);
            uint4 vl = *(const uint4*)(Blo + gi);
            int off = row * ASTR + k8 * 8;
            *(uint4*)&sBh[off] = vh;
            *(uint4*)&sBl[off] = vl;
        }
        __syncthreads();
        #pragma unroll
        for (int ks = 0; ks < KT; ks += 16) {
            u32 ah[4][4], al[4][4], bh[4][2], bl[4][2];
            #pragma unroll
            for (int mi = 0; mi < 4; mi++) {
                int r = (wm * 64 + mi * 16 + g) * ASTR + ks + tg * 2;
                ah[mi][0] = *(const u32*)&sAh[r];
                ah[mi][1] = *(const u32*)&sAh[r + 8 * ASTR];
                ah[mi][2] = *(const u32*)&sAh[r + 8];
                ah[mi][3] = *(const u32*)&sAh[r + 8 * ASTR + 8];
                al[mi][0] = *(const u32*)&sAl[r];
                al[mi][1] = *(const u32*)&sAl[r + 8 * ASTR];
                al[mi][2] = *(const u32*)&sAl[r + 8];
                al[mi][3] = *(const u32*)&sAl[r + 8 * ASTR + 8];
            }
            #pragma unroll
            for (int ni = 0; ni < 4; ni++) {
                int r = (wn * 32 + ni * 8 + g) * ASTR + ks + tg * 2;
                bh[ni][0] = *(const u32*)&sBh[r];
                bh[ni][1] = *(const u32*)&sBh[r + 8];
                bl[ni][0] = *(const u32*)&sBl[r];
                bl[ni][1] = *(const u32*)&sBl[r + 8];
            }
            #pragma unroll
            for (int mi = 0; mi < 4; mi++)
                #pragma unroll
                for (int ni = 0; ni < 4; ni++) {
                    mma_bf16(c[mi][ni], ah[mi], bh[ni]);
                    mma_bf16(c[mi][ni], ah[mi], bl[ni]);
                    mma_bf16(c[mi][ni], al[mi], bh[ni]);
                }
        }
        __syncthreads();
    }
    // ---- epilogue ----
    #pragma unroll
    for (int mi = 0; mi < 4; mi++) {
        int r = row0 + wm * 64 + mi * 16 + g;
        #pragma unroll
        for (int ni = 0; ni < 4; ni++) {
            int cc = col0 + wn * 32 + ni * 8 + tg * 2;
            if (r < M)
                *(float2*)(C + (size_t)r * ldc + cc) = make_float2(c[mi][ni][0], c[mi][ni][1]);
            if (r + 8 < M)
                *(float2*)(C + (size_t)(r + 8) * ldc + cc) = make_float2(c[mi][ni][2], c[mi][ni][3]);
        }
    }
}

// ---------------- aggregation (gather over CSR, float4 vectorized) ----------------
// conv1: block 128 = 4 warps; warp = segment (one of 4 convs), 32 lanes x float4.
__global__ __launch_bounds__(128) void k_agg1(
    const float* __restrict__ ea,
    const float* __restrict__ b1A, const float* __restrict__ b1B,
    const float* __restrict__ b1C, const float* __restrict__ b1D)
{
    int v = blockIdx.x;
    int wid = threadIdx.x >> 5, lane = threadIdx.x & 31;
    int beg = d_rowptr[v], end = d_rowptr[v + 1];
    const float* dis = d_dis4 + wid * NN;
    float dv = dis[v];
    float4 acc = make_float4(0.f, 0.f, 0.f, 0.f);
    for (int p = beg; p < end; ++p) {
        int s = d_csr_src[p];
        int e = d_csr_eid[p];
        float w = __ldg(ea + e * 4 + wid);
        float nrm = dis[s] * w * dv;
        float4 hv = *(const float4*)(d_h1lin + (size_t)s * 512 + wid * 128 + lane * 4);
        acc.x += hv.x * nrm; acc.y += hv.y * nrm;
        acc.z += hv.z * nrm; acc.w += hv.w * nrm;
    }
    float sn = dv * dv;
    float4 hv = *(const float4*)(d_h1lin + (size_t)v * 512 + wid * 128 + lane * 4);
    acc.x += hv.x * sn; acc.y += hv.y * sn; acc.z += hv.z * sn; acc.w += hv.w * sn;
    const float* bp = (wid == 0) ? b1A : (wid == 1) ? b1B : (wid == 2) ? b1C : b1D;
    float4 bb = *(const float4*)(bp + lane * 4);
    float4 o;
    o.x = fmaxf(acc.x + bb.x, 0.f); o.y = fmaxf(acc.y + bb.y, 0.f);
    o.z = fmaxf(acc.z + bb.z, 0.f); o.w = fmaxf(acc.w + bb.w, 0.f);
    *(float4*)(d_xcat + (size_t)v * 512 + wid * 128 + lane * 4) = o;
}

// conv2: 2 nodes per 128-thread block; 64 threads x float4 = 256 floats per node.
__global__ __launch_bounds__(128) void k_agg2(const float* __restrict__ b2) {
    int v = blockIdx.x * 2 + (threadIdx.x >> 6);
    int t6 = threadIdx.x & 63;
    if (v >= NN) return;
    int beg = d_rowptr[v], end = d_rowptr[v + 1];
    float dv = d_dis1[v];
    float4 acc = make_float4(0.f, 0.f, 0.f, 0.f);
    for (int p = beg; p < end; ++p) {
        int s = d_csr_src[p];
        float nrm = d_dis1[s] * dv;
        float4 hv = *(const float4*)(d_h2lin + (size_t)s * 256 + t6 * 4);
        acc.x += hv.x * nrm; acc.y += hv.y * nrm;
        acc.z += hv.z * nrm; acc.w += hv.w * nrm;
    }
    float sn = dv * dv;
    float4 hv = *(const float4*)(d_h2lin + (size_t)v * 256 + t6 * 4);
    acc.x += hv.x * sn; acc.y += hv.y * sn; acc.z += hv.z * sn; acc.w += hv.w * sn;
    float4 bb = *(const float4*)(b2 + t6 * 4);
    float4 o;
    o.x = fmaxf(acc.x + bb.x, 0.f); o.y = fmaxf(acc.y + bb.y, 0.f);
    o.z = fmaxf(acc.z + bb.z, 0.f); o.w = fmaxf(acc.w + bb.w, 0.f);
    *(float4*)(d_h2 + (size_t)v * 256 + t6 * 4) = o;
}

// conv3: 4 nodes per 128-thread block; 32 lanes x float4 = 128 floats per node.
__global__ __launch_bounds__(128) void k_agg3(const float* __restrict__ b3) {
    int v = blockIdx.x * 4 + (threadIdx.x >> 5);
    int lane = threadIdx.x & 31;
    if (v >= NN) return;
    int beg = d_rowptr[v], end = d_rowptr[v + 1];
    float dv = d_dis1[v];
    float4 acc = make_float4(0.f, 0.f, 0.f, 0.f);
    for (int p = beg; p < end; ++p) {
        int s = d_csr_src[p];
        float nrm = d_dis1[s] * dv;
        float4 hv = *(const float4*)(d_h3lin + (size_t)s * 128 + lane * 4);
        acc.x += hv.x * nrm; acc.y += hv.y * nrm;
        acc.z += hv.z * nrm; acc.w += hv.w * nrm;
    }
    float sn = dv * dv;
    float4 hv = *(const float4*)(d_h3lin + (size_t)v * 128 + lane * 4);
    float4 bb = *(const float4*)(b3 + lane * 4);
    float4 o;
    o.x = acc.x + hv.x * sn + bb.x; o.y = acc.y + hv.y * sn + bb.y;
    o.z = acc.z + hv.z * sn + bb.z; o.w = acc.w + hv.w * sn + bb.w;
    *(float4*)(d_h3 + (size_t)v * 128 + lane * 4) = o;
}

// ---------------- pooling + head ----------------
__global__ void k_bounds(const int* __restrict__ batch) {
    int i = blockIdx.x * blockDim.x + threadIdx.x;
    if (i >= NN) return;
    int b = batch[i];
    if (i == 0) {
        for (int g = 0; g <= b; ++g) d_gstart[g] = 0;
    } else {
        int pb = batch[i - 1];
        if (pb != b)
            for (int g = pb + 1; g <= b; ++g) d_gstart[g] = i;
    }
    if (i == NN - 1) {
        for (int g = b + 1; g <= NG; ++g) d_gstart[g] = NN;
    }
}

__global__ __launch_bounds__(128) void k_pool() {
    __shared__ float4 ssum[4][32], smax[4][32];
    int g = blockIdx.x;
    int wid = threadIdx.x >> 5, lane = threadIdx.x & 31;
    int beg = d_gstart[g], end = d_gstart[g + 1];
    int cnt = end - beg;
    float4 s = make_float4(0.f, 0.f, 0.f, 0.f);
    float4 m = make_float4(-INFINITY, -INFINITY, -INFINITY, -INFINITY);
    for (int i = beg + wid; i < end; i += 4) {
        float4 v = *(const float4*)(d_h3 + (size_t)i * 128 + lane * 4);
        s.x += v.x; s.y += v.y; s.z += v.z; s.w += v.w;
        m.x = fmaxf(m.x, v.x); m.y = fmaxf(m.y, v.y);
        m.z = fmaxf(m.z, v.z); m.w = fmaxf(m.w, v.w);
    }
    ssum[wid][lane] = s; smax[wid][lane] = m;
    __syncthreads();
    if (wid == 0) {
        #pragma unroll
        for (int w = 1; w < 4; ++w) {
            float4 s2 = ssum[w][lane], m2 = smax[w][lane];
            s.x += s2.x; s.y += s2.y; s.z += s2.z; s.w += s2.w;
            m.x = fmaxf(m.x, m2.x); m.y = fmaxf(m.y, m2.y);
            m.z = fmaxf(m.z, m2.z); m.w = fmaxf(m.w, m2.w);
        }
        float inv = 1.0f / fmaxf((float)cnt, 1.0f);
        float4 mean = make_float4(s.x * inv, s.y * inv, s.z * inv, s.w * inv);
        if (cnt == 0) m = make_float4(0.f, 0.f, 0.f, 0.f);
        *(float4*)(d_gmat + g * 256 + lane * 4) = mean;
        *(float4*)(d_gmat + g * 256 + 128 + lane * 4) = m;
    }
}

__global__ void k_mlp(const float* __restrict__ Wm1, const float* __restrict__ bm1,
                      const float* __restrict__ Wm2, const float* __restrict__ bm2,
                      float* __restrict__ out) {
    int g = threadIdx.x;
    if (g >= NG) return;
    const float* gv = d_gmat + g * 256;
    float hid[8];
    #pragma unroll
    for (int j = 0; j < 8; ++j) {
        float s = bm1[j];
        for (int k = 0; k < 256; ++k) s += gv[k] * Wm1[k * 8 + j];
        hid[j] = fmaxf(s, 0.f);
    }
    #pragma unroll
    for (int c = 0; c < 2; ++c) {
        float o = bm2[c];
        #pragma unroll
        for (int j = 0; j < 8; ++j) o += hid[j] * Wm2[j * 2 + c];
        out[g * 2 + c] = o;
    }
}

// ---------------- launch ----------------
extern "C" void kernel_launch(void* const* d_in, const int* in_sizes, int n_in,
                              void* d_out, int out_size) {
    const float* x   = (const float*)d_in[0];
    const int*   ei  = (const int*)d_in[1];
    const float* ea  = (const float*)d_in[2];
    const int*   bat = (const int*)d_in[3];
    const float* W1A = (const float*)d_in[4];  const float* b1A = (const float*)d_in[5];
    const float* W1B = (const float*)d_in[6];  const float* b1B = (const float*)d_in[7];
    const float* W1C = (const float*)d_in[8];  const float* b1C = (const float*)d_in[9];
    const float* W1D = (const float*)d_in[10]; const float* b1D = (const float*)d_in[11];
    const float* W2  = (const float*)d_in[12]; const float* b2  = (const float*)d_in[13];
    const float* W3  = (const float*)d_in[14]; const float* b3  = (const float*)d_in[15];
    const float* Wm1 = (const float*)d_in[16]; const float* bm1 = (const float*)d_in[17];
    const float* Wm2 = (const float*)d_in[18]; const float* bm2 = (const float*)d_in[19];
    float* out = (float*)d_out;

    float *h1lin, *xcat, *h2lin, *h2, *h3lin;
    unsigned short *wc_hi, *wc_lo, *w2_hi, *w2_lo, *w3_hi, *w3_lo;
    cudaGetSymbolAddress((void**)&h1lin, d_h1lin);
    cudaGetSymbolAddress((void**)&xcat,  d_xcat);
    cudaGetSymbolAddress((void**)&h2lin, d_h2lin);
    cudaGetSymbolAddress((void**)&h2,    d_h2);
    cudaGetSymbolAddress((void**)&h3lin, d_h3lin);
    cudaGetSymbolAddress((void**)&wc_hi, d_wc_hi);
    cudaGetSymbolAddress((void**)&wc_lo, d_wc_lo);
    cudaGetSymbolAddress((void**)&w2_hi, d_w2_hi);
    cudaGetSymbolAddress((void**)&w2_lo, d_w2_lo);
    cudaGetSymbolAddress((void**)&w3_hi, d_w3_hi);
    cudaGetSymbolAddress((void**)&w3_lo, d_w3_lo);

    const int TB = 256;
    k_init  <<<196 + 896, 256>>>(W1A, W1B, W1C, W1D, W2, W3);       // 1
    k_degree<<<(NE + TB - 1) / TB, TB>>>(ei, ea);                   // 2
    k_rsqrt <<<(5 * NN + TB - 1) / TB, TB>>>();                     // 3

    // 4 (profiled): conv1 GEMM  h1lin[50000,512] = x[50000,128] @ Wcat_t^T
    mma_gemm<<<dim3(4, 391), 256>>>(x, wc_hi, wc_lo, h1lin, NN, 128, 512);

    k_bsum  <<<196, 256>>>();
    k_bscan <<<1, 256>>>();
    k_scan3 <<<196, 256>>>();
    k_scatter<<<(NE + TB - 1) / TB, TB>>>(ei);

    k_agg1<<<NN, 128>>>(ea, b1A, b1B, b1C, b1D);

    mma_gemm<<<dim3(2, 391), 256>>>(xcat, w2_hi, w2_lo, h2lin, NN, 512, 256);
    k_agg2<<<NN / 2, 128>>>(b2);

    mma_gemm<<<dim3(1, 391), 256>>>(h2, w3_hi, w3_lo, h3lin, NN, 256, 128);
    k_agg3<<<NN / 4, 128>>>(b3);

    k_bounds<<<(NN + TB - 1) / TB, TB>>>(bat);
    k_pool<<<NG, 128>>>();
    k_mlp<<<1, NG>>>(Wm1, bm1, Wm2, bm2, out);
}